// round 2
// baseline (speedup 1.0000x reference)
#include <cuda_runtime.h>
#include <cuda_bf16.h>

// Problem shapes
#define B_   1024
#define L_   200
#define DIM_ 100
#define NP   128          // padded N
#define KSPLIT 8
#define KCHUNK (B_ / KSPLIT)   // 128

// Scratch (allocation-free: __device__ globals)
__device__ __align__(256) float g_rel[B_ * NP];                 // mean-pooled, padded
__device__ __align__(256) float g_tmp[B_ * NP];                 // A @ rel
__device__ __align__(256) float g_part[KSPLIT * B_ * NP];       // split-K partials

// ---------------------------------------------------------------------------
// Kernel 1: gather + mean-pool.  rel[b][t] = (1/len[b]) * sum_l emb[items[b,l]][t]
// with emb[0] == zero row, emb[j>0] == item_embedding[j-1].
// NOTE: items is int32 (JAX x64 disabled downcasts jnp.int64 -> int32).
// One block per batch row, 128 threads (t<100 active for data, pad cols zeroed).
// ---------------------------------------------------------------------------
__global__ void gather_kernel(const float* __restrict__ emb,
                              const int* __restrict__ items,
                              const float* __restrict__ slen) {
    int b = blockIdx.x;
    int t = threadIdx.x;
    __shared__ int sidx[L_];
    for (int l = t; l < L_; l += 128) sidx[l] = items[b * L_ + l];
    __syncthreads();

    float acc = 0.f;
    if (t < DIM_) {
        #pragma unroll 4
        for (int l = 0; l < L_; l++) {
            int j = sidx[l];
            if (j > 0) acc += emb[(long long)(j - 1) * DIM_ + t];
        }
    }
    float inv = 1.f / slen[b];
    g_rel[b * NP + t] = (t < DIM_) ? acc * inv : 0.f;
}

// ---------------------------------------------------------------------------
// Kernel 2: split-K SGEMM.  P[chunk] += Asrc[64-row tile] @ Bsel  (N = 128)
// Block tile: BM=64, BN=128, per-block K range = 128, staged in BK=16 steps.
// 256 threads; warp ty owns rows [ty*8, ty*8+8), lane tx owns cols [tx*4, tx*4+4).
// selB: 0 -> g_rel, 1 -> g_tmp.
// ---------------------------------------------------------------------------
__global__ __launch_bounds__(256) void gemm_splitk(const float* __restrict__ A,
                                                   int selB) {
    const float* __restrict__ Bm = selB ? g_tmp : g_rel;
    __shared__ float As[16][64];
    __shared__ float Bs[16][NP];

    int tid = threadIdx.x;
    int tx = tid & 31;         // lane
    int ty = tid >> 5;         // warp 0..7
    int m0 = blockIdx.x * 64;
    int kbase = blockIdx.y * KCHUNK;

    float acc[8][4];
    #pragma unroll
    for (int i = 0; i < 8; i++)
        #pragma unroll
        for (int j = 0; j < 4; j++) acc[i][j] = 0.f;

    for (int kk = 0; kk < KCHUNK; kk += 16) {
        // --- load A tile (64 x 16), store transposed As[k][m] ---
        {
            int m  = tid >> 2;           // 0..63
            int k4 = (tid & 3) * 4;      // 0,4,8,12
            float4 v = *(const float4*)&A[(long long)(m0 + m) * B_ + kbase + kk + k4];
            As[k4 + 0][m] = v.x;
            As[k4 + 1][m] = v.y;
            As[k4 + 2][m] = v.z;
            As[k4 + 3][m] = v.w;
        }
        // --- load B tile (16 x 128) ---
        {
            int r  = tid >> 5;           // 0..7
            int c4 = (tid & 31) * 4;     // 0..124
            *(float4*)&Bs[r][c4]     = *(const float4*)&Bm[(kbase + kk + r) * NP + c4];
            *(float4*)&Bs[r + 8][c4] = *(const float4*)&Bm[(kbase + kk + r + 8) * NP + c4];
        }
        __syncthreads();

        #pragma unroll
        for (int k = 0; k < 16; k++) {
            float4 a0 = *(const float4*)&As[k][ty * 8];
            float4 a1 = *(const float4*)&As[k][ty * 8 + 4];
            float4 bv = *(const float4*)&Bs[k][tx * 4];
            float am[8] = {a0.x, a0.y, a0.z, a0.w, a1.x, a1.y, a1.z, a1.w};
            float bn[4] = {bv.x, bv.y, bv.z, bv.w};
            #pragma unroll
            for (int i = 0; i < 8; i++)
                #pragma unroll
                for (int j = 0; j < 4; j++)
                    acc[i][j] = fmaf(am[i], bn[j], acc[i][j]);
        }
        __syncthreads();
    }

    // write partials
    float* P = g_part + (long long)blockIdx.y * (B_ * NP);
    #pragma unroll
    for (int i = 0; i < 8; i++) {
        int m = m0 + ty * 8 + i;
        float4 v = make_float4(acc[i][0], acc[i][1], acc[i][2], acc[i][3]);
        *(float4*)&P[m * NP + tx * 4] = v;
    }
}

// ---------------------------------------------------------------------------
// Kernel 3: reduce split-K partials into g_tmp
// ---------------------------------------------------------------------------
__global__ void reduce_kernel() {
    int i = blockIdx.x * 256 + threadIdx.x;   // 0 .. 131071
    float s = 0.f;
    #pragma unroll
    for (int c = 0; c < KSPLIT; c++) s += g_part[c * (B_ * NP) + i];
    g_tmp[i] = s;
}

// ---------------------------------------------------------------------------
// Kernel 4: fused split-K reduce + SELU + L2 row-normalize -> out [1024,100]
// One block per row, 128 threads.
// ---------------------------------------------------------------------------
__global__ void epilogue_kernel(float* __restrict__ out) {
    int b = blockIdx.x;
    int t = threadIdx.x;

    float s = 0.f;
    #pragma unroll
    for (int c = 0; c < KSPLIT; c++) s += g_part[c * (B_ * NP) + b * NP + t];

    const float kScale = 1.0507009873554804934193349852946f;
    const float kAlpha = 1.6732632423543772848170429916717f;
    float cv = kScale * (s > 0.f ? s : kAlpha * (expf(s) - 1.f));

    float v = (t < DIM_) ? cv * cv : 0.f;
    // block reduction over 128 threads
    #pragma unroll
    for (int o = 16; o > 0; o >>= 1) v += __shfl_xor_sync(0xFFFFFFFFu, v, o);
    __shared__ float red[4];
    if ((t & 31) == 0) red[t >> 5] = v;
    __syncthreads();
    float nrm = rsqrtf(red[0] + red[1] + red[2] + red[3]);

    if (t < DIM_) out[b * DIM_ + t] = cv * nrm;
}

// ---------------------------------------------------------------------------
extern "C" void kernel_launch(void* const* d_in, const int* in_sizes, int n_in,
                              void* d_out, int out_size) {
    const float* emb   = (const float*)d_in[0];      // [50000,100] f32
    const int*   items = (const int*)d_in[1];        // [1024,200] int32 (JAX x64 off)
    const float* A     = (const float*)d_in[2];      // [1024,1024] f32
    const float* D     = (const float*)d_in[3];      // [1024,1024] f32
    const float* slen  = (const float*)d_in[4];      // [1024,1] f32
    float*       out   = (float*)d_out;              // [1024,100] f32

    gather_kernel<<<B_, 128>>>(emb, items, slen);

    dim3 ggrid(B_ / 64, KSPLIT);
    gemm_splitk<<<ggrid, 256>>>(A, /*selB=*/0);   // partials of A @ rel
    reduce_kernel<<<(B_ * NP) / 256, 256>>>();    // g_tmp = A @ rel
    gemm_splitk<<<ggrid, 256>>>(D, /*selB=*/1);   // partials of D @ (A @ rel)
    epilogue_kernel<<<B_, 128>>>(out);            // reduce + selu + L2 norm
}

// round 3
// speedup vs baseline: 1.1074x; 1.1074x over previous
#include <cuda_runtime.h>
#include <cuda_bf16.h>

// Problem shapes
#define B_   1024
#define L_   200
#define DIM_ 100
#define NP   128               // padded N
#define KSPLIT 16
#define KCHUNK (B_ / KSPLIT)   // 64

// Scratch (allocation-free: __device__ globals)
__device__ __align__(256) float g_rel[B_ * NP];                 // mean-pooled, padded
__device__ __align__(256) float g_tmp[B_ * NP];                 // A @ rel
__device__ __align__(256) float g_part[KSPLIT * B_ * NP];       // split-K partials

// ---------------------------------------------------------------------------
// Kernel 1: gather + mean-pool.  rel[b][t] = (1/len[b]) * sum_l emb[items[b,l]][t]
// items is int32 (JAX x64 disabled). One block per batch row, 128 threads.
// ---------------------------------------------------------------------------
__global__ void gather_kernel(const float* __restrict__ emb,
                              const int* __restrict__ items,
                              const float* __restrict__ slen) {
    int b = blockIdx.x;
    int t = threadIdx.x;
    __shared__ int sidx[L_];
    for (int l = t; l < L_; l += 128) sidx[l] = items[b * L_ + l];
    __syncthreads();

    float acc = 0.f;
    if (t < DIM_) {
        #pragma unroll 4
        for (int l = 0; l < L_; l++) {
            int j = sidx[l];
            if (j > 0) acc += emb[(long long)(j - 1) * DIM_ + t];
        }
    }
    float inv = 1.f / slen[b];
    g_rel[b * NP + t] = (t < DIM_) ? acc * inv : 0.f;
}

// ---------------------------------------------------------------------------
// Kernel 2: split-K SGEMM, double-buffered.  BM=64, BN=128, BK=16, KCHUNK=64.
// grid = (16, 16) = 256 blocks -> 2 blocks/SM. 256 threads.
// warp ty owns rows [ty*8, ty*8+8), lane tx owns cols [tx*4, tx*4+4).
// ---------------------------------------------------------------------------
__global__ __launch_bounds__(256, 2) void gemm_splitk(const float* __restrict__ A,
                                                      int selB) {
    const float* __restrict__ Bm = selB ? g_tmp : g_rel;
    __shared__ float As[2][16][64];
    __shared__ float Bs[2][16][NP];

    int tid = threadIdx.x;
    int tx = tid & 31;           // lane
    int ty = tid >> 5;           // warp 0..7
    int m0 = blockIdx.x * 64;
    int kbase = blockIdx.y * KCHUNK;

    // load-index decomposition
    int lm  = tid >> 2;          // A row within tile: 0..63
    int lk4 = (tid & 3) * 4;     // A k offset: 0,4,8,12
    int br  = tid >> 5;          // B row: 0..7 (and +8)
    int bc4 = (tid & 31) * 4;    // B col: 0..124

    const float* Arow = &A[(long long)(m0 + lm) * B_ + kbase + lk4];

    // prologue: tile 0 -> buffer 0
    {
        float4 v = *(const float4*)&Arow[0];
        As[0][lk4 + 0][lm] = v.x;
        As[0][lk4 + 1][lm] = v.y;
        As[0][lk4 + 2][lm] = v.z;
        As[0][lk4 + 3][lm] = v.w;
        *(float4*)&Bs[0][br][bc4]     = *(const float4*)&Bm[(kbase + br) * NP + bc4];
        *(float4*)&Bs[0][br + 8][bc4] = *(const float4*)&Bm[(kbase + br + 8) * NP + bc4];
    }
    __syncthreads();

    float acc[8][4];
    #pragma unroll
    for (int i = 0; i < 8; i++)
        #pragma unroll
        for (int j = 0; j < 4; j++) acc[i][j] = 0.f;

    const int T = KCHUNK / 16;   // 4 steps
    #pragma unroll
    for (int s = 0; s < T; s++) {
        float4 av, bv0, bv1;
        if (s + 1 < T) {
            int ko = (s + 1) * 16;
            av  = *(const float4*)&Arow[ko];
            bv0 = *(const float4*)&Bm[(kbase + ko + br) * NP + bc4];
            bv1 = *(const float4*)&Bm[(kbase + ko + br + 8) * NP + bc4];
        }
        int cb = s & 1;
        #pragma unroll
        for (int k = 0; k < 16; k++) {
            float4 a0 = *(const float4*)&As[cb][k][ty * 8];
            float4 a1 = *(const float4*)&As[cb][k][ty * 8 + 4];
            float4 bv = *(const float4*)&Bs[cb][k][tx * 4];
            float am[8] = {a0.x, a0.y, a0.z, a0.w, a1.x, a1.y, a1.z, a1.w};
            float bn[4] = {bv.x, bv.y, bv.z, bv.w};
            #pragma unroll
            for (int i = 0; i < 8; i++)
                #pragma unroll
                for (int j = 0; j < 4; j++)
                    acc[i][j] = fmaf(am[i], bn[j], acc[i][j]);
        }
        if (s + 1 < T) {
            int nb = cb ^ 1;
            As[nb][lk4 + 0][lm] = av.x;
            As[nb][lk4 + 1][lm] = av.y;
            As[nb][lk4 + 2][lm] = av.z;
            As[nb][lk4 + 3][lm] = av.w;
            *(float4*)&Bs[nb][br][bc4]     = bv0;
            *(float4*)&Bs[nb][br + 8][bc4] = bv1;
            __syncthreads();
        }
    }

    // write partials
    float* P = g_part + (long long)blockIdx.y * (B_ * NP);
    #pragma unroll
    for (int i = 0; i < 8; i++) {
        int m = m0 + ty * 8 + i;
        *(float4*)&P[m * NP + tx * 4] =
            make_float4(acc[i][0], acc[i][1], acc[i][2], acc[i][3]);
    }
}

// ---------------------------------------------------------------------------
// Kernel 3: reduce split-K partials into g_tmp
// ---------------------------------------------------------------------------
__global__ void reduce_kernel() {
    int i = blockIdx.x * 256 + threadIdx.x;   // 0 .. 131071
    float s = 0.f;
    #pragma unroll
    for (int c = 0; c < KSPLIT; c++) s += g_part[c * (B_ * NP) + i];
    g_tmp[i] = s;
}

// ---------------------------------------------------------------------------
// Kernel 4: fused split-K reduce + SELU + L2 row-normalize -> out [1024,100]
// ---------------------------------------------------------------------------
__global__ void epilogue_kernel(float* __restrict__ out) {
    int b = blockIdx.x;
    int t = threadIdx.x;

    float s = 0.f;
    #pragma unroll
    for (int c = 0; c < KSPLIT; c++) s += g_part[c * (B_ * NP) + b * NP + t];

    const float kScale = 1.0507009873554804934193349852946f;
    const float kAlpha = 1.6732632423543772848170429916717f;
    float cv = kScale * (s > 0.f ? s : kAlpha * (expf(s) - 1.f));

    float v = (t < DIM_) ? cv * cv : 0.f;
    #pragma unroll
    for (int o = 16; o > 0; o >>= 1) v += __shfl_xor_sync(0xFFFFFFFFu, v, o);
    __shared__ float red[4];
    if ((t & 31) == 0) red[t >> 5] = v;
    __syncthreads();
    float nrm = rsqrtf(red[0] + red[1] + red[2] + red[3]);

    if (t < DIM_) out[b * DIM_ + t] = cv * nrm;
}

// ---------------------------------------------------------------------------
extern "C" void kernel_launch(void* const* d_in, const int* in_sizes, int n_in,
                              void* d_out, int out_size) {
    const float* emb   = (const float*)d_in[0];      // [50000,100] f32
    const int*   items = (const int*)d_in[1];        // [1024,200] int32
    const float* A     = (const float*)d_in[2];      // [1024,1024] f32
    const float* D     = (const float*)d_in[3];      // [1024,1024] f32
    const float* slen  = (const float*)d_in[4];      // [1024,1] f32
    float*       out   = (float*)d_out;              // [1024,100] f32

    gather_kernel<<<B_, 128>>>(emb, items, slen);

    dim3 ggrid(B_ / 64, KSPLIT);                  // (16,16) = 256 blocks
    gemm_splitk<<<ggrid, 256>>>(A, /*selB=*/0);   // partials of A @ rel
    reduce_kernel<<<(B_ * NP) / 256, 256>>>();    // g_tmp = A @ rel
    gemm_splitk<<<ggrid, 256>>>(D, /*selB=*/1);   // partials of D @ (A @ rel)
    epilogue_kernel<<<B_, 128>>>(out);            // reduce + selu + L2 norm
}

// round 4
// speedup vs baseline: 1.3683x; 1.2356x over previous
#include <cuda_runtime.h>
#include <cuda_bf16.h>

typedef unsigned long long u64;

// Problem shapes
#define B_   1024
#define L_   200
#define DIM_ 100
#define NP   128               // padded N
#define KSPLIT 16
#define KCHUNK (B_ / KSPLIT)   // 64

// Scratch (allocation-free: __device__ globals)
__device__ __align__(256) float g_rel[B_ * NP];                 // mean-pooled, padded
__device__ __align__(256) float g_tmp[B_ * NP];                 // A @ rel
__device__ __align__(256) float g_part[KSPLIT * B_ * NP];       // split-K partials

// ---------------------------------------------------------------------------
// packed f32x2 helpers (sm_103a)
// ---------------------------------------------------------------------------
__device__ __forceinline__ void fma2(u64& d, u64 a, u64 b) {
    asm("fma.rn.f32x2 %0, %1, %2, %0;" : "+l"(d) : "l"(a), "l"(b));
}
__device__ __forceinline__ u64 pack2(float x) {
    u64 r;
    asm("mov.b64 %0, {%1, %1};" : "=l"(r) : "f"(x));
    return r;
}
__device__ __forceinline__ void unpack2(u64 v, float& lo, float& hi) {
    asm("mov.b64 {%0, %1}, %2;" : "=f"(lo), "=f"(hi) : "l"(v));
}

// ---------------------------------------------------------------------------
// Kernel 1: gather + mean-pool.  rel[b][t] = (1/len[b]) * sum_l emb[items[b,l]][t]
// 256 threads: warp w handles rows l in [w*25, w*25+25); lanes 0..24 each own
// one float4 column segment (25*4 = 100). emb rows are 400B -> 16B aligned.
// ---------------------------------------------------------------------------
__global__ __launch_bounds__(256) void gather_kernel(const float* __restrict__ emb,
                                                     const int* __restrict__ items,
                                                     const float* __restrict__ slen) {
    int b = blockIdx.x;
    int t = threadIdx.x;
    int w = t >> 5;              // warp 0..7
    int c = t & 31;              // lane

    __shared__ int sidx[L_];
    __shared__ float spart[8][DIM_];

    for (int l = t; l < L_; l += 256) sidx[l] = items[b * L_ + l];
    __syncthreads();

    float4 acc = make_float4(0.f, 0.f, 0.f, 0.f);
    if (c < 25) {
        int l0 = w * 25;
        #pragma unroll 5
        for (int l = l0; l < l0 + 25; l++) {
            int j = sidx[l];
            if (j > 0) {
                float4 v = *(const float4*)&emb[(long long)(j - 1) * DIM_ + c * 4];
                acc.x += v.x; acc.y += v.y; acc.z += v.z; acc.w += v.w;
            }
        }
        spart[w][c * 4 + 0] = acc.x;
        spart[w][c * 4 + 1] = acc.y;
        spart[w][c * 4 + 2] = acc.z;
        spart[w][c * 4 + 3] = acc.w;
    }
    __syncthreads();

    if (t < NP) {
        float s = 0.f;
        if (t < DIM_) {
            #pragma unroll
            for (int ww = 0; ww < 8; ww++) s += spart[ww][t];
            s *= 1.f / slen[b];
        }
        g_rel[b * NP + t] = s;
    }
}

// ---------------------------------------------------------------------------
// Kernel 2: split-K SGEMM with packed fma.rn.f32x2.
// BM=64, BN=128, BK=16, KCHUNK=64, grid (16,16), 256 threads, double-buffered.
// warp ty owns rows [ty*8, ty*8+8) (as 4 m-pairs), lane tx owns cols [tx*4,+4).
// ---------------------------------------------------------------------------
__global__ __launch_bounds__(256, 2) void gemm_splitk(const float* __restrict__ A,
                                                      int selB) {
    const float* __restrict__ Bm = selB ? g_tmp : g_rel;
    __shared__ float As[2][16][64];      // [k][m], m contiguous -> free m-pairs
    __shared__ float Bs[2][16][NP];

    int tid = threadIdx.x;
    int tx = tid & 31;           // lane
    int ty = tid >> 5;           // warp 0..7
    int m0 = blockIdx.x * 64;
    int kbase = blockIdx.y * KCHUNK;

    int lm  = tid >> 2;          // A row within tile: 0..63
    int lk4 = (tid & 3) * 4;     // A k offset: 0,4,8,12
    int br  = tid >> 5;          // B row: 0..7 (and +8)
    int bc4 = (tid & 31) * 4;    // B col: 0..124

    const float* Arow = &A[(long long)(m0 + lm) * B_ + kbase + lk4];

    // prologue: tile 0 -> buffer 0
    {
        float4 v = *(const float4*)&Arow[0];
        As[0][lk4 + 0][lm] = v.x;
        As[0][lk4 + 1][lm] = v.y;
        As[0][lk4 + 2][lm] = v.z;
        As[0][lk4 + 3][lm] = v.w;
        *(float4*)&Bs[0][br][bc4]     = *(const float4*)&Bm[(kbase + br) * NP + bc4];
        *(float4*)&Bs[0][br + 8][bc4] = *(const float4*)&Bm[(kbase + br + 8) * NP + bc4];
    }
    __syncthreads();

    u64 acc2[4][4];              // [m-pair][n], pair = rows (2*i2, 2*i2+1)
    #pragma unroll
    for (int i = 0; i < 4; i++)
        #pragma unroll
        for (int j = 0; j < 4; j++) acc2[i][j] = 0ULL;

    const int T = KCHUNK / 16;   // 4 steps
    #pragma unroll
    for (int s = 0; s < T; s++) {
        float4 av, bv0, bv1;
        if (s + 1 < T) {
            int ko = (s + 1) * 16;
            av  = *(const float4*)&Arow[ko];
            bv0 = *(const float4*)&Bm[(kbase + ko + br) * NP + bc4];
            bv1 = *(const float4*)&Bm[(kbase + ko + br + 8) * NP + bc4];
        }
        int cb = s & 1;
        #pragma unroll
        for (int k = 0; k < 16; k++) {
            ulonglong2 p0 = *(const ulonglong2*)&As[cb][k][ty * 8];      // (m0,m1),(m2,m3)
            ulonglong2 p1 = *(const ulonglong2*)&As[cb][k][ty * 8 + 4];  // (m4,m5),(m6,m7)
            float4 bv = *(const float4*)&Bs[cb][k][tx * 4];
            u64 a2[4] = {p0.x, p0.y, p1.x, p1.y};
            u64 b2[4] = {pack2(bv.x), pack2(bv.y), pack2(bv.z), pack2(bv.w)};
            #pragma unroll
            for (int i = 0; i < 4; i++)
                #pragma unroll
                for (int j = 0; j < 4; j++)
                    fma2(acc2[i][j], a2[i], b2[j]);
        }
        if (s + 1 < T) {
            int nb = cb ^ 1;
            As[nb][lk4 + 0][lm] = av.x;
            As[nb][lk4 + 1][lm] = av.y;
            As[nb][lk4 + 2][lm] = av.z;
            As[nb][lk4 + 3][lm] = av.w;
            *(float4*)&Bs[nb][br][bc4]     = bv0;
            *(float4*)&Bs[nb][br + 8][bc4] = bv1;
            __syncthreads();
        }
    }

    // unpack + write partials
    float* P = g_part + (long long)blockIdx.y * (B_ * NP);
    #pragma unroll
    for (int i2 = 0; i2 < 4; i2++) {
        float r0[4], r1[4];
        #pragma unroll
        for (int j = 0; j < 4; j++) unpack2(acc2[i2][j], r0[j], r1[j]);
        int m = m0 + ty * 8 + i2 * 2;
        *(float4*)&P[(m + 0) * NP + tx * 4] = make_float4(r0[0], r0[1], r0[2], r0[3]);
        *(float4*)&P[(m + 1) * NP + tx * 4] = make_float4(r1[0], r1[1], r1[2], r1[3]);
    }
}

// ---------------------------------------------------------------------------
// Kernel 3: reduce split-K partials into g_tmp (float4 vectorized)
// ---------------------------------------------------------------------------
__global__ void reduce_kernel() {
    int i = (blockIdx.x * 256 + threadIdx.x) * 4;   // 0 .. 131068
    float4 s = make_float4(0.f, 0.f, 0.f, 0.f);
    #pragma unroll
    for (int c = 0; c < KSPLIT; c++) {
        float4 v = *(const float4*)&g_part[c * (B_ * NP) + i];
        s.x += v.x; s.y += v.y; s.z += v.z; s.w += v.w;
    }
    *(float4*)&g_tmp[i] = s;
}

// ---------------------------------------------------------------------------
// Kernel 4: fused split-K reduce + SELU + L2 row-normalize -> out [1024,100]
// ---------------------------------------------------------------------------
__global__ void epilogue_kernel(float* __restrict__ out) {
    int b = blockIdx.x;
    int t = threadIdx.x;

    float s = 0.f;
    #pragma unroll
    for (int c = 0; c < KSPLIT; c++) s += g_part[c * (B_ * NP) + b * NP + t];

    const float kScale = 1.0507009873554804934193349852946f;
    const float kAlpha = 1.6732632423543772848170429916717f;
    float cv = kScale * (s > 0.f ? s : kAlpha * (expf(s) - 1.f));

    float v = (t < DIM_) ? cv * cv : 0.f;
    #pragma unroll
    for (int o = 16; o > 0; o >>= 1) v += __shfl_xor_sync(0xFFFFFFFFu, v, o);
    __shared__ float red[4];
    if ((t & 31) == 0) red[t >> 5] = v;
    __syncthreads();
    float nrm = rsqrtf(red[0] + red[1] + red[2] + red[3]);

    if (t < DIM_) out[b * DIM_ + t] = cv * nrm;
}

// ---------------------------------------------------------------------------
extern "C" void kernel_launch(void* const* d_in, const int* in_sizes, int n_in,
                              void* d_out, int out_size) {
    const float* emb   = (const float*)d_in[0];      // [50000,100] f32
    const int*   items = (const int*)d_in[1];        // [1024,200] int32
    const float* A     = (const float*)d_in[2];      // [1024,1024] f32
    const float* D     = (const float*)d_in[3];      // [1024,1024] f32
    const float* slen  = (const float*)d_in[4];      // [1024,1] f32
    float*       out   = (float*)d_out;              // [1024,100] f32

    gather_kernel<<<B_, 256>>>(emb, items, slen);

    dim3 ggrid(B_ / 64, KSPLIT);                  // (16,16) = 256 blocks
    gemm_splitk<<<ggrid, 256>>>(A, /*selB=*/0);   // partials of A @ rel
    reduce_kernel<<<(B_ * NP) / 1024, 256>>>();   // g_tmp = A @ rel
    gemm_splitk<<<ggrid, 256>>>(D, /*selB=*/1);   // partials of D @ (A @ rel)
    epilogue_kernel<<<B_, 128>>>(out);            // reduce + selu + L2 norm
}